// round 1
// baseline (speedup 1.0000x reference)
#include <cuda_runtime.h>
#include <math.h>

#define SEQ   2048
#define DMODEL 768
#define NHEAD 12
#define DH    64
#define FFDIM 3072
#define NLAYER 12
#define WIN   256
#define LNEPS 1e-5f

// ---------------- scratch (no allocation allowed) ----------------
__device__ float g_h [SEQ * DMODEL];
__device__ float g_q [SEQ * DMODEL];
__device__ float g_k [SEQ * DMODEL];
__device__ float g_v [SEQ * DMODEL];
__device__ float g_ao[SEQ * DMODEL];
__device__ float g_t2[SEQ * DMODEL];
__device__ float g_ff[SEQ * FFDIM];
__device__ int   g_pos[SEQ];

// ---------------- position ids (serial, trivial cost) ----------------
__global__ void pos_ids_kernel(const int* __restrict__ mask) {
    int c = 0;
    for (int i = 0; i < SEQ; i++) {
        c += mask[i];
        g_pos[i] = c * mask[i] + 1;
    }
}

// ---------------- embedding gather ----------------
__global__ void embed_kernel(const int* __restrict__ ids,
                             const float* __restrict__ we,
                             const float* __restrict__ pe,
                             const float* __restrict__ te,
                             float* __restrict__ out) {
    int s = blockIdx.x;
    int id = ids[s];
    int p  = g_pos[s];
    const float* wrow = we + (long)id * DMODEL;
    const float* prow = pe + (long)p  * DMODEL;
    for (int d = threadIdx.x; d < DMODEL; d += blockDim.x)
        out[s * DMODEL + d] = wrow[d] + prow[d] + te[d];
}

// ---------------- LayerNorm (optionally adds residual) ----------------
// one block per row, 256 threads, 3 elements per thread (768 = 3*256)
__global__ void ln_kernel(const float* __restrict__ x,
                          const float* __restrict__ res,   // may be null
                          const float* __restrict__ g,
                          const float* __restrict__ b,
                          float* __restrict__ out) {
    int row = blockIdx.x;
    int t = threadIdx.x;
    const float* xp = x + row * DMODEL;
    const float* rp = res ? res + row * DMODEL : nullptr;

    float v[3];
    float s = 0.f;
#pragma unroll
    for (int i = 0; i < 3; i++) {
        float u = xp[t + i * 256];
        if (rp) u += rp[t + i * 256];
        v[i] = u;
        s += u;
    }
    __shared__ float red[8];
    __shared__ float stats[2];
#pragma unroll
    for (int o = 16; o; o >>= 1) s += __shfl_xor_sync(0xffffffffu, s, o);
    if ((t & 31) == 0) red[t >> 5] = s;
    __syncthreads();
    if (t == 0) {
        float z = 0.f;
        for (int i = 0; i < 8; i++) z += red[i];
        stats[0] = z * (1.f / DMODEL);
    }
    __syncthreads();
    float m = stats[0];
    float sq = 0.f;
#pragma unroll
    for (int i = 0; i < 3; i++) {
        float d0 = v[i] - m;
        sq += d0 * d0;
    }
#pragma unroll
    for (int o = 16; o; o >>= 1) sq += __shfl_xor_sync(0xffffffffu, sq, o);
    if ((t & 31) == 0) red[t >> 5] = sq;
    __syncthreads();
    if (t == 0) {
        float z = 0.f;
        for (int i = 0; i < 8; i++) z += red[i];
        stats[1] = rsqrtf(z * (1.f / DMODEL) + LNEPS);
    }
    __syncthreads();
    float r = stats[1];
#pragma unroll
    for (int i = 0; i < 3; i++) {
        int c = t + i * 256;
        out[row * DMODEL + c] = (v[i] - m) * r * g[c] + b[c];
    }
}

// ---------------- SGEMM: C[M,N] = A[M,K] @ B[K,N] + bias, ACT=1 -> exact GELU
// BM=BN=64, BK=16, 256 threads, 4x4 microtile. All dims divisible (M=2048,
// N in {768,3072}, K in {768,3072}).
template <int ACT>
__global__ void __launch_bounds__(256)
gemm_kernel(const float* __restrict__ A, const float* __restrict__ B,
            const float* __restrict__ bias, float* __restrict__ C,
            int M, int N, int K) {
    __shared__ __align__(16) float As[16][68];
    __shared__ __align__(16) float Bs[16][68];

    int tid = threadIdx.x;
    int tx = tid & 15;
    int ty = tid >> 4;
    int rowBase = blockIdx.y * 64;
    int colBase = blockIdx.x * 64;

    float acc[4][4] = {};

    for (int k0 = 0; k0 < K; k0 += 16) {
#pragma unroll
        for (int i = 0; i < 4; i++) {
            int lin = tid + i * 256;
            int r  = lin >> 4;
            int kk = lin & 15;
            As[kk][r] = A[(rowBase + r) * K + k0 + kk];
            int kb = lin >> 6;
            int cb = lin & 63;
            Bs[kb][cb] = B[(k0 + kb) * N + colBase + cb];
        }
        __syncthreads();
#pragma unroll
        for (int kk = 0; kk < 16; kk++) {
            float4 a4 = *(const float4*)&As[kk][ty * 4];
            float4 b4 = *(const float4*)&Bs[kk][tx * 4];
            float av[4] = {a4.x, a4.y, a4.z, a4.w};
            float bv[4] = {b4.x, b4.y, b4.z, b4.w};
#pragma unroll
            for (int i = 0; i < 4; i++)
#pragma unroll
                for (int j = 0; j < 4; j++)
                    acc[i][j] += av[i] * bv[j];
        }
        __syncthreads();
    }

#pragma unroll
    for (int i = 0; i < 4; i++) {
        int r = rowBase + ty * 4 + i;
#pragma unroll
        for (int j = 0; j < 4; j++) {
            int c = colBase + tx * 4 + j;
            float val = acc[i][j] + bias[c];
            if (ACT == 1)
                val = 0.5f * val * (1.f + erff(val * 0.70710678118654752f));
            C[r * N + c] = val;
        }
    }
}

// ---------------- banded (sliding-window) attention ----------------
// grid (SEQ/64, NHEAD), 256 threads. 64-query tile, 32-key tiles,
// online softmax. Matches HF Longformer banded mask (|i-j|<=WIN, key_mask).
#define QT 64
#define KT 32
#define DSTR 68
#define SSTR 36

__global__ void __launch_bounds__(256)
attn_kernel(const float* __restrict__ q, const float* __restrict__ k,
            const float* __restrict__ v, const int* __restrict__ mask,
            float* __restrict__ out) {
    __shared__ __align__(16) float qs[QT][DSTR];
    __shared__ __align__(16) float ks[KT][DSTR];
    __shared__ __align__(16) float vs[KT][DSTR];
    __shared__ __align__(16) float ss[QT][SSTR];
    __shared__ float m_s[QT], l_s[QT], scale_s[QT];

    int c = blockIdx.x;
    int h = blockIdx.y;
    int tid = threadIdx.x;
    int q0 = c * QT;

    // load Q tile, fold 1/sqrt(dh)=0.125
#pragma unroll
    for (int i = 0; i < 16; i++) {
        int lin = tid + i * 256;
        int r = lin >> 6, d = lin & 63;
        qs[r][d] = q[(q0 + r) * DMODEL + h * DH + d] * 0.125f;
    }
    if (tid < QT) { m_s[tid] = -1e30f; l_s[tid] = 0.f; }

    float acc[16] = {};
    int qlocal = tid >> 2;
    int dg = (tid & 3) * 16;
    __syncthreads();

    int jstart = q0 - WIN;
#pragma unroll 1
    for (int t = 0; t < (2 * WIN + QT) / KT; t++) {   // 18 tiles
        int j0 = jstart + t * KT;
        if (j0 + KT <= 0 || j0 >= SEQ) continue;      // uniform across block

        // load K,V tiles (guard sequence boundaries)
#pragma unroll
        for (int i = 0; i < 8; i++) {
            int lin = tid + i * 256;
            int r = lin >> 6, d = lin & 63;
            int kj = j0 + r;
            bool ok = (kj >= 0) && (kj < SEQ);
            ks[r][d] = ok ? k[kj * DMODEL + h * DH + d] : 0.f;
            vs[r][d] = ok ? v[kj * DMODEL + h * DH + d] : 0.f;
        }
        __syncthreads();

        // scores: thread -> (ql, 8 consecutive keys)
        {
            int ql = tid >> 2;
            int kb = (tid & 3) * 8;
            float sc[8] = {};
#pragma unroll
            for (int d = 0; d < DH; d += 4) {
                float4 qv = *(const float4*)&qs[ql][d];
#pragma unroll
                for (int j = 0; j < 8; j++) {
                    float4 kv = *(const float4*)&ks[kb + j][d];
                    sc[j] += qv.x * kv.x + qv.y * kv.y + qv.z * kv.z + qv.w * kv.w;
                }
            }
            int qi = q0 + ql;
#pragma unroll
            for (int j = 0; j < 8; j++) {
                int kj = j0 + kb + j;
                bool valid = (kj >= 0) && (kj < SEQ) &&
                             (qi - kj <= WIN) && (kj - qi <= WIN) &&
                             (mask[(kj >= 0 && kj < SEQ) ? kj : 0] != 0);
                ss[ql][kb + j] = valid ? sc[j] : -1e9f;
            }
        }
        __syncthreads();

        // per-row online softmax update (threads 0..63)
        if (tid < QT) {
            float mo = m_s[tid];
            float mx = mo;
            for (int j = 0; j < KT; j++) mx = fmaxf(mx, ss[tid][j]);
            float scl = expf(mo - mx);
            float sum = 0.f;
            for (int j = 0; j < KT; j++) {
                float p = expf(ss[tid][j] - mx);
                ss[tid][j] = p;
                sum += p;
            }
            m_s[tid] = mx;
            l_s[tid] = l_s[tid] * scl + sum;
            scale_s[tid] = scl;
        }
        __syncthreads();

        // P @ V, thread owns (qlocal, 16 dims)
        {
            float scl = scale_s[qlocal];
#pragma unroll
            for (int i = 0; i < 16; i++) acc[i] *= scl;
            for (int kk = 0; kk < KT; kk++) {
                float p = ss[qlocal][kk];
#pragma unroll
                for (int i = 0; i < 16; i += 4) {
                    float4 vv = *(const float4*)&vs[kk][dg + i];
                    acc[i]     += p * vv.x;
                    acc[i + 1] += p * vv.y;
                    acc[i + 2] += p * vv.z;
                    acc[i + 3] += p * vv.w;
                }
            }
        }
        __syncthreads();   // protect ks/vs/ss before next tile
    }

    float inv = 1.f / l_s[qlocal];
#pragma unroll
    for (int i = 0; i < 16; i++)
        out[(q0 + qlocal) * DMODEL + h * DH + dg + i] = acc[i] * inv;
}

// ---------------- final extract: h[0, :] ----------------
__global__ void out_kernel(float* __restrict__ out) {
    out[threadIdx.x] = g_h[threadIdx.x];
}

// ---------------- launcher ----------------
extern "C" void kernel_launch(void* const* d_in, const int* in_sizes, int n_in,
                              void* d_out, int out_size) {
    const int*   ids  = (const int*)  d_in[0];
    const int*   am   = (const int*)  d_in[1];
    const float* we   = (const float*)d_in[2];
    const float* pe   = (const float*)d_in[3];
    const float* te   = (const float*)d_in[4];
    const float* eg   = (const float*)d_in[5];
    const float* eb   = (const float*)d_in[6];
    const float* Wq   = (const float*)d_in[7];
    const float* bq   = (const float*)d_in[8];
    const float* Wk   = (const float*)d_in[9];
    const float* bk   = (const float*)d_in[10];
    const float* Wv   = (const float*)d_in[11];
    const float* bv   = (const float*)d_in[12];
    const float* Wo   = (const float*)d_in[13];
    const float* bo   = (const float*)d_in[14];
    const float* g1   = (const float*)d_in[15];
    const float* b1   = (const float*)d_in[16];
    const float* W1   = (const float*)d_in[17];
    const float* c1   = (const float*)d_in[18];
    const float* W2   = (const float*)d_in[19];
    const float* c2   = (const float*)d_in[20];
    const float* g2   = (const float*)d_in[21];
    const float* b2   = (const float*)d_in[22];

    float *h, *qb, *kb, *vb, *ao, *t2, *ffb;
    cudaGetSymbolAddress((void**)&h,  g_h);
    cudaGetSymbolAddress((void**)&qb, g_q);
    cudaGetSymbolAddress((void**)&kb, g_k);
    cudaGetSymbolAddress((void**)&vb, g_v);
    cudaGetSymbolAddress((void**)&ao, g_ao);
    cudaGetSymbolAddress((void**)&t2, g_t2);
    cudaGetSymbolAddress((void**)&ffb, g_ff);

    pos_ids_kernel<<<1, 1>>>(am);
    embed_kernel<<<SEQ, 256>>>(ids, we, pe, te, t2);
    ln_kernel<<<SEQ, 256>>>(t2, nullptr, eg, eb, h);

    dim3 gProj(DMODEL / 64, SEQ / 64);   // 12 x 32
    dim3 gFF1 (FFDIM  / 64, SEQ / 64);   // 48 x 32
    dim3 gAttn(SEQ / QT, NHEAD);         // 32 x 12

    for (int l = 0; l < NLAYER; l++) {
        const float* wq = Wq + (long)l * DMODEL * DMODEL;
        const float* wk = Wk + (long)l * DMODEL * DMODEL;
        const float* wv = Wv + (long)l * DMODEL * DMODEL;
        const float* wo = Wo + (long)l * DMODEL * DMODEL;
        const float* w1 = W1 + (long)l * DMODEL * FFDIM;
        const float* w2 = W2 + (long)l * FFDIM * DMODEL;

        gemm_kernel<0><<<gProj, 256>>>(h, wq, bq + l * DMODEL, qb, SEQ, DMODEL, DMODEL);
        gemm_kernel<0><<<gProj, 256>>>(h, wk, bk + l * DMODEL, kb, SEQ, DMODEL, DMODEL);
        gemm_kernel<0><<<gProj, 256>>>(h, wv, bv + l * DMODEL, vb, SEQ, DMODEL, DMODEL);

        attn_kernel<<<gAttn, 256>>>(qb, kb, vb, am, ao);

        gemm_kernel<0><<<gProj, 256>>>(ao, wo, bo + l * DMODEL, t2, SEQ, DMODEL, DMODEL);
        ln_kernel<<<SEQ, 256>>>(t2, h, g1 + l * DMODEL, b1 + l * DMODEL, h);

        gemm_kernel<1><<<gFF1, 256>>>(h, w1, c1 + l * FFDIM, ffb, SEQ, FFDIM, DMODEL);
        gemm_kernel<0><<<gProj, 256>>>(ffb, w2, c2 + l * DMODEL, t2, SEQ, DMODEL, FFDIM);
        ln_kernel<<<SEQ, 256>>>(t2, h, g2 + l * DMODEL, b2 + l * DMODEL, h);
    }

    out_kernel<<<1, DMODEL>>>((float*)d_out);
}

// round 2
// speedup vs baseline: 1.3719x; 1.3719x over previous
#include <cuda_runtime.h>
#include <math.h>

#define SEQ   2048
#define DMODEL 768
#define NHEAD 12
#define DH    64
#define FFDIM 3072
#define NLAYER 12
#define WIN   256
#define LNEPS 1e-5f

// ---------------- scratch (no allocation allowed) ----------------
__device__ float g_h [SEQ * DMODEL];
__device__ float g_q [SEQ * DMODEL];
__device__ float g_k [SEQ * DMODEL];
__device__ float g_v [SEQ * DMODEL];
__device__ float g_ao[SEQ * DMODEL];
__device__ float g_t2[SEQ * DMODEL];
__device__ float g_ff[SEQ * FFDIM];
__device__ int   g_pos[SEQ];

// ---------------- position ids: single-block parallel scan ----------------
__global__ void pos_ids_kernel(const int* __restrict__ mask) {   // 256 threads
    int t = threadIdx.x;
    int v[8], s = 0;
#pragma unroll
    for (int i = 0; i < 8; i++) { v[i] = mask[t * 8 + i]; s += v[i]; }
    int lane = t & 31, w = t >> 5;
    int x = s;
#pragma unroll
    for (int o = 1; o < 32; o <<= 1) {
        int y = __shfl_up_sync(0xffffffffu, x, o);
        if (lane >= o) x += y;
    }
    __shared__ int wt[8];
    if (lane == 31) wt[w] = x;
    __syncthreads();
    int wo = 0;
    for (int i = 0; i < w; i++) wo += wt[i];
    int run = wo + x - s;            // exclusive prefix for this thread
#pragma unroll
    for (int i = 0; i < 8; i++) {
        run += v[i];
        g_pos[t * 8 + i] = run * v[i] + 1;
    }
}

// ---------------- embedding gather (192 threads, float4) ----------------
__global__ void embed_kernel(const int* __restrict__ ids,
                             const float* __restrict__ we,
                             const float* __restrict__ pe,
                             const float* __restrict__ te,
                             float* __restrict__ out) {
    int s = blockIdx.x;
    int t = threadIdx.x;
    int id = ids[s];
    int p  = g_pos[s];
    float4 a = *(const float4*)&we[(long)id * DMODEL + t * 4];
    float4 b = *(const float4*)&pe[(long)p  * DMODEL + t * 4];
    float4 c = *(const float4*)&te[t * 4];
    float4 o = {a.x + b.x + c.x, a.y + b.y + c.y, a.z + b.z + c.z, a.w + b.w + c.w};
    *(float4*)&out[s * DMODEL + t * 4] = o;
}

// ---------------- LayerNorm (+optional residual), 192 threads, float4 ----------------
__global__ void ln_kernel(const float* __restrict__ x,
                          const float* __restrict__ res,   // may be null
                          const float* __restrict__ g,
                          const float* __restrict__ b,
                          float* __restrict__ out) {
    int row = blockIdx.x;
    int t = threadIdx.x;
    float4 u = *(const float4*)&x[row * DMODEL + t * 4];
    if (res) {
        float4 r4 = *(const float4*)&res[row * DMODEL + t * 4];
        u.x += r4.x; u.y += r4.y; u.z += r4.z; u.w += r4.w;
    }
    float s = u.x + u.y + u.z + u.w;
    __shared__ float red[6];
    __shared__ float stats[2];
#pragma unroll
    for (int o = 16; o; o >>= 1) s += __shfl_xor_sync(0xffffffffu, s, o);
    if ((t & 31) == 0) red[t >> 5] = s;
    __syncthreads();
    if (t == 0) {
        float z = 0.f;
        for (int i = 0; i < 6; i++) z += red[i];
        stats[0] = z * (1.f / DMODEL);
    }
    __syncthreads();
    float m = stats[0];
    float dx = u.x - m, dy = u.y - m, dz = u.z - m, dw = u.w - m;
    float sq = dx * dx + dy * dy + dz * dz + dw * dw;
#pragma unroll
    for (int o = 16; o; o >>= 1) sq += __shfl_xor_sync(0xffffffffu, sq, o);
    if ((t & 31) == 0) red[t >> 5] = sq;
    __syncthreads();
    if (t == 0) {
        float z = 0.f;
        for (int i = 0; i < 6; i++) z += red[i];
        stats[1] = rsqrtf(z * (1.f / DMODEL) + LNEPS);
    }
    __syncthreads();
    float r = stats[1];
    float4 g4 = *(const float4*)&g[t * 4];
    float4 b4 = *(const float4*)&b[t * 4];
    float4 o;
    o.x = dx * r * g4.x + b4.x;
    o.y = dy * r * g4.y + b4.y;
    o.z = dz * r * g4.z + b4.z;
    o.w = dw * r * g4.w + b4.w;
    *(float4*)&out[row * DMODEL + t * 4] = o;
}

// ---------------- SGEMM v2: 128x64 tile, BK=16, 8x4 microtile, double-buffered
// C[M,N] = A[M,K] @ B[K,N] + bias; ACT=1 -> exact GELU
template <int ACT>
__global__ void __launch_bounds__(256)
gemm_kernel(const float* __restrict__ A, const float* __restrict__ B,
            const float* __restrict__ bias, float* __restrict__ C,
            int M, int N, int K) {
    __shared__ __align__(16) float As[2][16][132];   // [buf][k][row]
    __shared__ __align__(16) float Bs[2][16][72];    // [buf][k][col]

    int tid = threadIdx.x;
    int tx = tid & 15;          // 16 col groups of 4
    int ty = tid >> 4;          // 16 row groups of 8
    int rowBase = blockIdx.y * 128;
    int colBase = blockIdx.x * 64;

    // global-load indices
    int ar0 = tid >> 2;               // 0..63   (idx0 rows)
    int ak0 = (tid & 3) << 2;         // k offset
    int ar1 = (tid + 256) >> 2;       // 64..127
    int bk  = tid >> 4;               // 0..15
    int bc  = (tid & 15) << 2;        // 0..60

    const float* Ap0 = A + (long)(rowBase + ar0) * K + ak0;
    const float* Ap1 = A + (long)(rowBase + ar1) * K + ak0;
    const float* Bp  = B + (long)bk * N + colBase + bc;

    float acc[8][4] = {};

    // fetch + store tile 0
    float4 pa0 = *(const float4*)Ap0;
    float4 pa1 = *(const float4*)Ap1;
    float4 pb  = *(const float4*)Bp;
    As[0][ak0 + 0][ar0] = pa0.x; As[0][ak0 + 1][ar0] = pa0.y;
    As[0][ak0 + 2][ar0] = pa0.z; As[0][ak0 + 3][ar0] = pa0.w;
    As[0][ak0 + 0][ar1] = pa1.x; As[0][ak0 + 1][ar1] = pa1.y;
    As[0][ak0 + 2][ar1] = pa1.z; As[0][ak0 + 3][ar1] = pa1.w;
    *(float4*)&Bs[0][bk][bc] = pb;
    __syncthreads();

    int cur = 0;
    int ntiles = K >> 4;
    for (int t = 0; t < ntiles; t++) {
        bool hn = (t + 1) < ntiles;
        if (hn) {
            int k0n = (t + 1) << 4;
            pa0 = *(const float4*)(Ap0 + k0n);
            pa1 = *(const float4*)(Ap1 + k0n);
            pb  = *(const float4*)(Bp + (long)k0n * N);
        }
#pragma unroll
        for (int kk = 0; kk < 16; kk++) {
            float a[8], b[4];
            *(float4*)&a[0] = *(const float4*)&As[cur][kk][ty * 8];
            *(float4*)&a[4] = *(const float4*)&As[cur][kk][ty * 8 + 4];
            *(float4*)&b[0] = *(const float4*)&Bs[cur][kk][tx * 4];
#pragma unroll
            for (int i = 0; i < 8; i++)
#pragma unroll
                for (int j = 0; j < 4; j++)
                    acc[i][j] = fmaf(a[i], b[j], acc[i][j]);
        }
        if (hn) {
            int nb = cur ^ 1;
            As[nb][ak0 + 0][ar0] = pa0.x; As[nb][ak0 + 1][ar0] = pa0.y;
            As[nb][ak0 + 2][ar0] = pa0.z; As[nb][ak0 + 3][ar0] = pa0.w;
            As[nb][ak0 + 0][ar1] = pa1.x; As[nb][ak0 + 1][ar1] = pa1.y;
            As[nb][ak0 + 2][ar1] = pa1.z; As[nb][ak0 + 3][ar1] = pa1.w;
            *(float4*)&Bs[nb][bk][bc] = pb;
            __syncthreads();
            cur = nb;
        }
    }

    float4 bb = *(const float4*)&bias[colBase + tx * 4];
#pragma unroll
    for (int i = 0; i < 8; i++) {
        int r = rowBase + ty * 8 + i;
        float4 o;
        o.x = acc[i][0] + bb.x;
        o.y = acc[i][1] + bb.y;
        o.z = acc[i][2] + bb.z;
        o.w = acc[i][3] + bb.w;
        if (ACT == 1) {
            o.x = 0.5f * o.x * (1.f + erff(o.x * 0.70710678118654752f));
            o.y = 0.5f * o.y * (1.f + erff(o.y * 0.70710678118654752f));
            o.z = 0.5f * o.z * (1.f + erff(o.z * 0.70710678118654752f));
            o.w = 0.5f * o.w * (1.f + erff(o.w * 0.70710678118654752f));
        }
        *(float4*)&C[(long)r * N + colBase + tx * 4] = o;
    }
}

// ---------------- banded (sliding-window) attention v2 ----------------
// grid (SEQ/64, NHEAD), 256 threads. Quad-per-query-row online softmax in
// registers, conflict-free key interleaving (key = quad + 4*j).
__global__ void __launch_bounds__(256)
attn_kernel(const float* __restrict__ q, const float* __restrict__ k,
            const float* __restrict__ v, const int* __restrict__ mask,
            float* __restrict__ out) {
    __shared__ __align__(16) float qs[64][68];
    __shared__ __align__(16) float ks[32][68];
    __shared__ __align__(16) float vs[32][68];
    __shared__ __align__(16) float ss[64][36];

    int c = blockIdx.x, h = blockIdx.y, tid = threadIdx.x;
    int q0 = c * 64;
    int base = h * DH;

    // load Q tile (fold 1/sqrt(dh) = 0.125)
#pragma unroll
    for (int i = 0; i < 4; i++) {
        int idx = tid + i * 256;
        int r = idx >> 4, dq = (idx & 15) << 2;
        float4 qv = *(const float4*)&q[(q0 + r) * DMODEL + base + dq];
        qv.x *= 0.125f; qv.y *= 0.125f; qv.z *= 0.125f; qv.w *= 0.125f;
        *(float4*)&qs[r][dq] = qv;
    }
    int ql = tid >> 2;
    int quad = tid & 3;
    int dg = quad << 4;
    float m = -1e30f, l = 0.f;
    float acc[16] = {};
    __syncthreads();

#pragma unroll 1
    for (int t = 0; t < (2 * WIN + 64) / 32; t++) {   // 18 tiles
        int j0 = q0 - WIN + t * 32;
        if (j0 + 32 <= 0 || j0 >= SEQ) continue;      // uniform across block

#pragma unroll
        for (int i = 0; i < 2; i++) {
            int idx = tid + i * 256;
            int r = idx >> 4, dq = (idx & 15) << 2;
            int kj = j0 + r;
            if (kj >= 0 && kj < SEQ) {
                *(float4*)&ks[r][dq] = *(const float4*)&k[kj * DMODEL + base + dq];
                *(float4*)&vs[r][dq] = *(const float4*)&v[kj * DMODEL + base + dq];
            } else {
                float4 z = {0.f, 0.f, 0.f, 0.f};
                *(float4*)&ks[r][dq] = z;
                *(float4*)&vs[r][dq] = z;
            }
        }
        __syncthreads();

        // scores: this thread -> (ql, keys quad+4j)
        float sc[8];
#pragma unroll
        for (int j = 0; j < 8; j++) sc[j] = 0.f;
#pragma unroll
        for (int d = 0; d < DH; d += 4) {
            float4 qv = *(const float4*)&qs[ql][d];
#pragma unroll
            for (int j = 0; j < 8; j++) {
                float4 kv = *(const float4*)&ks[quad + (j << 2)][d];
                sc[j] += qv.x * kv.x + qv.y * kv.y + qv.z * kv.z + qv.w * kv.w;
            }
        }
        int qi = q0 + ql;
        float tm = -1e30f;
#pragma unroll
        for (int j = 0; j < 8; j++) {
            int kj = j0 + quad + (j << 2);
            bool valid = (kj >= 0) && (kj < SEQ) &&
                         (qi - kj <= WIN) && (kj - qi <= WIN) && (mask[kj] != 0);
            if (!valid) sc[j] = -1e9f;
            tm = fmaxf(tm, sc[j]);
        }
        tm = fmaxf(tm, __shfl_xor_sync(0xffffffffu, tm, 1));
        tm = fmaxf(tm, __shfl_xor_sync(0xffffffffu, tm, 2));
        float mn = fmaxf(m, tm);
        float scl = __expf(m - mn);
        float ps = 0.f;
#pragma unroll
        for (int j = 0; j < 8; j++) {
            float p = __expf(sc[j] - mn);
            ss[ql][quad + (j << 2)] = p;
            ps += p;
        }
        ps += __shfl_xor_sync(0xffffffffu, ps, 1);
        ps += __shfl_xor_sync(0xffffffffu, ps, 2);
        m = mn;
        l = l * scl + ps;
#pragma unroll
        for (int i = 0; i < 16; i++) acc[i] *= scl;
        __syncthreads();

        // P @ V: thread owns (ql, 16 dims at dg)
#pragma unroll 4
        for (int kk = 0; kk < 32; kk++) {
            float p = ss[ql][kk];
#pragma unroll
            for (int i = 0; i < 16; i += 4) {
                float4 vv = *(const float4*)&vs[kk][dg + i];
                acc[i]     += p * vv.x;
                acc[i + 1] += p * vv.y;
                acc[i + 2] += p * vv.z;
                acc[i + 3] += p * vv.w;
            }
        }
        __syncthreads();   // protect ks/vs/ss before next tile
    }

    float inv = 1.f / l;
#pragma unroll
    for (int i = 0; i < 16; i += 4) {
        float4 o = {acc[i] * inv, acc[i + 1] * inv, acc[i + 2] * inv, acc[i + 3] * inv};
        *(float4*)&out[(q0 + ql) * DMODEL + base + dg + i] = o;
    }
}

// ---------------- final extract: h[0, :] ----------------
__global__ void out_kernel(float* __restrict__ out) {
    out[threadIdx.x] = g_h[threadIdx.x];
}

// ---------------- launcher ----------------
extern "C" void kernel_launch(void* const* d_in, const int* in_sizes, int n_in,
                              void* d_out, int out_size) {
    const int*   ids  = (const int*)  d_in[0];
    const int*   am   = (const int*)  d_in[1];
    const float* we   = (const float*)d_in[2];
    const float* pe   = (const float*)d_in[3];
    const float* te   = (const float*)d_in[4];
    const float* eg   = (const float*)d_in[5];
    const float* eb   = (const float*)d_in[6];
    const float* Wq   = (const float*)d_in[7];
    const float* bq   = (const float*)d_in[8];
    const float* Wk   = (const float*)d_in[9];
    const float* bk   = (const float*)d_in[10];
    const float* Wv   = (const float*)d_in[11];
    const float* bv   = (const float*)d_in[12];
    const float* Wo   = (const float*)d_in[13];
    const float* bo   = (const float*)d_in[14];
    const float* g1   = (const float*)d_in[15];
    const float* b1   = (const float*)d_in[16];
    const float* W1   = (const float*)d_in[17];
    const float* c1   = (const float*)d_in[18];
    const float* W2   = (const float*)d_in[19];
    const float* c2   = (const float*)d_in[20];
    const float* g2   = (const float*)d_in[21];
    const float* b2   = (const float*)d_in[22];

    float *h, *qb2, *kb2, *vb2, *ao, *t2, *ffb;
    cudaGetSymbolAddress((void**)&h,   g_h);
    cudaGetSymbolAddress((void**)&qb2, g_q);
    cudaGetSymbolAddress((void**)&kb2, g_k);
    cudaGetSymbolAddress((void**)&vb2, g_v);
    cudaGetSymbolAddress((void**)&ao,  g_ao);
    cudaGetSymbolAddress((void**)&t2,  g_t2);
    cudaGetSymbolAddress((void**)&ffb, g_ff);

    pos_ids_kernel<<<1, 256>>>(am);
    embed_kernel<<<SEQ, 192>>>(ids, we, pe, te, t2);
    ln_kernel<<<SEQ, 192>>>(t2, nullptr, eg, eb, h);

    dim3 gProj(DMODEL / 64, SEQ / 128);   // 12 x 16
    dim3 gFF1 (FFDIM  / 64, SEQ / 128);   // 48 x 16
    dim3 gAttn(SEQ / 64, NHEAD);          // 32 x 12

    for (int l = 0; l < NLAYER; l++) {
        const float* wq = Wq + (long)l * DMODEL * DMODEL;
        const float* wk = Wk + (long)l * DMODEL * DMODEL;
        const float* wv = Wv + (long)l * DMODEL * DMODEL;
        const float* wo = Wo + (long)l * DMODEL * DMODEL;
        const float* w1 = W1 + (long)l * DMODEL * FFDIM;
        const float* w2 = W2 + (long)l * FFDIM * DMODEL;

        gemm_kernel<0><<<gProj, 256>>>(h, wq, bq + l * DMODEL, qb2, SEQ, DMODEL, DMODEL);
        gemm_kernel<0><<<gProj, 256>>>(h, wk, bk + l * DMODEL, kb2, SEQ, DMODEL, DMODEL);
        gemm_kernel<0><<<gProj, 256>>>(h, wv, bv + l * DMODEL, vb2, SEQ, DMODEL, DMODEL);

        attn_kernel<<<gAttn, 256>>>(qb2, kb2, vb2, am, ao);

        gemm_kernel<0><<<gProj, 256>>>(ao, wo, bo + l * DMODEL, t2, SEQ, DMODEL, DMODEL);
        ln_kernel<<<SEQ, 192>>>(t2, h, g1 + l * DMODEL, b1 + l * DMODEL, h);

        gemm_kernel<1><<<gFF1, 256>>>(h, w1, c1 + l * FFDIM, ffb, SEQ, FFDIM, DMODEL);
        gemm_kernel<0><<<gProj, 256>>>(ffb, w2, c2 + l * DMODEL, t2, SEQ, DMODEL, FFDIM);
        ln_kernel<<<SEQ, 192>>>(t2, h, g2 + l * DMODEL, b2 + l * DMODEL, h);
    }

    out_kernel<<<1, DMODEL>>>((float*)d_out);
}

// round 6
// speedup vs baseline: 2.4975x; 1.8205x over previous
#include <cuda_runtime.h>
#include <cuda_bf16.h>
#include <math.h>
#include <stdint.h>

#define SEQ    2048
#define DMODEL 768
#define NHEAD  12
#define DH     64
#define FFDIM  3072
#define NLAYER 12
#define WIN    256
#define LNEPS  1e-5f
#define QKVD   2304

// ---------------- static scratch ----------------
__device__ __nv_bfloat16 g_wqkv_hi[NLAYER * QKVD * DMODEL];
__device__ __nv_bfloat16 g_wqkv_lo[NLAYER * QKVD * DMODEL];
__device__ __nv_bfloat16 g_wo_hi[NLAYER * DMODEL * DMODEL];
__device__ __nv_bfloat16 g_wo_lo[NLAYER * DMODEL * DMODEL];
__device__ __nv_bfloat16 g_w1_hi[NLAYER * FFDIM * DMODEL];
__device__ __nv_bfloat16 g_w1_lo[NLAYER * FFDIM * DMODEL];
__device__ __nv_bfloat16 g_w2_hi[NLAYER * DMODEL * FFDIM];
__device__ __nv_bfloat16 g_w2_lo[NLAYER * DMODEL * FFDIM];
__device__ float g_bqkv[NLAYER * QKVD];

__device__ float g_h  [SEQ * DMODEL];
__device__ __nv_bfloat16 g_h_hi[SEQ * DMODEL];
__device__ __nv_bfloat16 g_h_lo[SEQ * DMODEL];
__device__ float g_qkv[SEQ * QKVD];
__device__ __nv_bfloat16 g_ao_hi[SEQ * DMODEL];
__device__ __nv_bfloat16 g_ao_lo[SEQ * DMODEL];
__device__ float g_t2 [SEQ * DMODEL];
__device__ __nv_bfloat16 g_ff_hi[SEQ * FFDIM];
__device__ __nv_bfloat16 g_ff_lo[SEQ * FFDIM];
__device__ int g_pos[SEQ];

// ---------------- helpers ----------------
__device__ __forceinline__ uint32_t smem_u32(const void* p) {
    uint32_t a;
    asm("{ .reg .u64 t; cvta.to.shared.u64 t, %1; cvt.u32.u64 %0, t; }"
        : "=r"(a) : "l"(p));
    return a;
}
__device__ __forceinline__ uint32_t swz(uint32_t off) {
    return off ^ ((off >> 3) & 0x70);
}
__device__ __forceinline__ void cp16(uint32_t dst, const void* src) {
    asm volatile("cp.async.cg.shared.global [%0], [%1], 16;" :: "r"(dst), "l"(src));
}
#define CP_COMMIT() asm volatile("cp.async.commit_group;" ::: "memory")
#define CP_WAIT1()  asm volatile("cp.async.wait_group 1;" ::: "memory")
#define CP_WAIT0()  asm volatile("cp.async.wait_group 0;" ::: "memory")

__device__ __forceinline__ void ldmx4(uint32_t* d, uint32_t addr) {
    asm volatile("ldmatrix.sync.aligned.m8n8.x4.shared.b16 {%0,%1,%2,%3}, [%4];"
        : "=r"(d[0]), "=r"(d[1]), "=r"(d[2]), "=r"(d[3]) : "r"(addr));
}
__device__ __forceinline__ void hmma(float* d, const uint32_t* a, const uint32_t* b) {
    asm volatile(
        "mma.sync.aligned.m16n8k16.row.col.f32.bf16.bf16.f32 "
        "{%0,%1,%2,%3}, {%4,%5,%6,%7}, {%8,%9}, {%0,%1,%2,%3};"
        : "+f"(d[0]), "+f"(d[1]), "+f"(d[2]), "+f"(d[3])
        : "r"(a[0]), "r"(a[1]), "r"(a[2]), "r"(a[3]), "r"(b[0]), "r"(b[1]));
}
__device__ __forceinline__ void split_bf16(float x, __nv_bfloat16& h, __nv_bfloat16& l) {
    h = __float2bfloat16(x);
    l = __float2bfloat16(x - __bfloat162float(h));
}

// ---------------- weight transpose + hi/lo split ----------------
__global__ void wconv_kernel(const float* __restrict__ in,
                             __nv_bfloat16* __restrict__ oh,
                             __nv_bfloat16* __restrict__ ol,
                             int K, int N, long in_ls, long out_ls, int row_off) {
    __shared__ float t[32][33];
    int l = blockIdx.z;
    const float* ip = in + (long)l * in_ls;
    long ob = (long)l * out_ls + (long)row_off * K;
    int k0 = blockIdx.y << 5, n0 = blockIdx.x << 5;
    int tx = threadIdx.x & 31, ty = threadIdx.x >> 5;
#pragma unroll
    for (int i = 0; i < 4; i++)
        t[ty + 8 * i][tx] = ip[(long)(k0 + ty + 8 * i) * N + n0 + tx];
    __syncthreads();
#pragma unroll
    for (int i = 0; i < 4; i++) {
        int n = ty + 8 * i;
        float x = t[tx][n];
        __nv_bfloat16 h, lo;
        split_bf16(x, h, lo);
        long o = ob + (long)(n0 + n) * K + k0 + tx;
        oh[o] = h;
        ol[o] = lo;
    }
}

__global__ void bmerge_kernel(const float* __restrict__ bq,
                              const float* __restrict__ bk,
                              const float* __restrict__ bv) {
    int l = blockIdx.x, t = threadIdx.x;
    g_bqkv[l * QKVD + t]        = bq[l * DMODEL + t];
    g_bqkv[l * QKVD + 768 + t]  = bk[l * DMODEL + t];
    g_bqkv[l * QKVD + 1536 + t] = bv[l * DMODEL + t];
}

// ---------------- position ids ----------------
__global__ void pos_ids_kernel(const int* __restrict__ mask) {
    int t = threadIdx.x;
    int v[8], s = 0;
#pragma unroll
    for (int i = 0; i < 8; i++) { v[i] = mask[t * 8 + i]; s += v[i]; }
    int lane = t & 31, w = t >> 5;
    int x = s;
#pragma unroll
    for (int o = 1; o < 32; o <<= 1) {
        int y = __shfl_up_sync(0xffffffffu, x, o);
        if (lane >= o) x += y;
    }
    __shared__ int wt[8];
    if (lane == 31) wt[w] = x;
    __syncthreads();
    int wo = 0;
    for (int i = 0; i < w; i++) wo += wt[i];
    int run = wo + x - s;
#pragma unroll
    for (int i = 0; i < 8; i++) {
        run += v[i];
        g_pos[t * 8 + i] = run * v[i] + 1;
    }
}

// ---------------- embedding gather ----------------
__global__ void embed_kernel(const int* __restrict__ ids,
                             const float* __restrict__ we,
                             const float* __restrict__ pe,
                             const float* __restrict__ te,
                             float* __restrict__ out) {
    int s = blockIdx.x, t = threadIdx.x;
    int id = ids[s];
    int p  = g_pos[s];
    float4 a = *(const float4*)&we[(long)id * DMODEL + t * 4];
    float4 b = *(const float4*)&pe[(long)p  * DMODEL + t * 4];
    float4 c = *(const float4*)&te[t * 4];
    float4 o = {a.x + b.x + c.x, a.y + b.y + c.y, a.z + b.z + c.z, a.w + b.w + c.w};
    *(float4*)&out[s * DMODEL + t * 4] = o;
}

// ---------------- LayerNorm (+residual) with optional bf16 hi/lo emit ----------------
__global__ void ln_kernel(const float* __restrict__ x,
                          const float* __restrict__ res,
                          const float* __restrict__ g,
                          const float* __restrict__ b,
                          float* __restrict__ out,
                          __nv_bfloat16* __restrict__ ohi,
                          __nv_bfloat16* __restrict__ olo) {
    int row = blockIdx.x, t = threadIdx.x;
    float4 u = *(const float4*)&x[row * DMODEL + t * 4];
    if (res) {
        float4 r4 = *(const float4*)&res[row * DMODEL + t * 4];
        u.x += r4.x; u.y += r4.y; u.z += r4.z; u.w += r4.w;
    }
    float s = u.x + u.y + u.z + u.w;
    __shared__ float red[6];
    __shared__ float stats[2];
#pragma unroll
    for (int o = 16; o; o >>= 1) s += __shfl_xor_sync(0xffffffffu, s, o);
    if ((t & 31) == 0) red[t >> 5] = s;
    __syncthreads();
    if (t == 0) {
        float z = 0.f;
        for (int i = 0; i < 6; i++) z += red[i];
        stats[0] = z * (1.f / DMODEL);
    }
    __syncthreads();
    float m = stats[0];
    float dx = u.x - m, dy = u.y - m, dz = u.z - m, dw = u.w - m;
    float sq = dx * dx + dy * dy + dz * dz + dw * dw;
#pragma unroll
    for (int o = 16; o; o >>= 1) sq += __shfl_xor_sync(0xffffffffu, sq, o);
    if ((t & 31) == 0) red[t >> 5] = sq;
    __syncthreads();
    if (t == 0) {
        float z = 0.f;
        for (int i = 0; i < 6; i++) z += red[i];
        stats[1] = rsqrtf(z * (1.f / DMODEL) + LNEPS);
    }
    __syncthreads();
    float r = stats[1];
    float4 g4 = *(const float4*)&g[t * 4];
    float4 b4 = *(const float4*)&b[t * 4];
    float4 o;
    o.x = dx * r * g4.x + b4.x;
    o.y = dy * r * g4.y + b4.y;
    o.z = dz * r * g4.z + b4.z;
    o.w = dw * r * g4.w + b4.w;
    *(float4*)&out[row * DMODEL + t * 4] = o;
    if (ohi) {
        __nv_bfloat16 h0, l0, h1, l1, h2, l2, h3, l3;
        split_bf16(o.x, h0, l0); split_bf16(o.y, h1, l1);
        split_bf16(o.z, h2, l2); split_bf16(o.w, h3, l3);
        __nv_bfloat162 hh0 = {h0, h1}, hh1 = {h2, h3};
        __nv_bfloat162 ll0 = {l0, l1}, ll1 = {l2, l3};
        uint2 ph = {*(uint32_t*)&hh0, *(uint32_t*)&hh1};
        uint2 pl = {*(uint32_t*)&ll0, *(uint32_t*)&ll1};
        *(uint2*)&ohi[row * DMODEL + t * 4] = ph;
        *(uint2*)&olo[row * DMODEL + t * 4] = pl;
    }
}

// ---------------- mma.sync bf16 split GEMM ----------------
// C[M,N] = A @ B^T (+bias). A:[M,K] hi/lo bf16, B:[N,K] hi/lo bf16.
// CTA 128x128, BK=64, 8 warps (4Mx2N), warp tile 32x64.
// smem: 2 stages x {Ahi,Alo,Bhi,Blo} x 16KB = 128KB.
#define STG 65536
#define P_AHI 0
#define P_ALO 16384
#define P_BHI 32768
#define P_BLO 49152

template <int ACT, int WF32, int WBF16>
__global__ void __launch_bounds__(256)
mgemm(const __nv_bfloat16* __restrict__ Ahi, const __nv_bfloat16* __restrict__ Alo,
      const __nv_bfloat16* __restrict__ Bhi, const __nv_bfloat16* __restrict__ Blo,
      const float* __restrict__ bias,
      float* __restrict__ C, __nv_bfloat16* __restrict__ Chi,
      __nv_bfloat16* __restrict__ Clo, int K, int ldC) {
    extern __shared__ char smem[];
    uint32_t sb = smem_u32(smem);
    int tid = threadIdx.x, wid = tid >> 5, lane = tid & 31;
    int m0 = blockIdx.y << 7, n0 = blockIdx.x << 7;
    int mw = (wid >> 1) << 5;      // warp M offset (0,32,64,96)
    int nw = (wid & 1) << 6;       // warp N offset (0,64)

    float acc[2][8][4];
#pragma unroll
    for (int i = 0; i < 2; i++)
#pragma unroll
        for (int j = 0; j < 8; j++)
#pragma unroll
            for (int q = 0; q < 4; q++) acc[i][j][q] = 0.f;

    int nchunks = K >> 6;

    // async load of one stage (4 chunks of 16B per thread per part)
    auto load_stage = [&](int ch, int stage) {
        uint32_t base = sb + stage * STG;
        long kOff = (long)(ch << 6);
#pragma unroll
        for (int i = 0; i < 4; i++) {
            int c = tid + (i << 8);
            int row = c >> 3;
            int cb  = (c & 7) << 4;          // byte col
            uint32_t so = swz((uint32_t)(row * 128 + cb));
            long ea = (long)(m0 + row) * K + kOff + ((c & 7) << 3);
            long eb = (long)(n0 + row) * K + kOff + ((c & 7) << 3);
            cp16(base + P_AHI + so, Ahi + ea);
            cp16(base + P_ALO + so, Alo + ea);
            cp16(base + P_BHI + so, Bhi + eb);
            cp16(base + P_BLO + so, Blo + eb);
        }
        CP_COMMIT();
    };

    load_stage(0, 0);
    if (nchunks > 1) load_stage(1, 1);

    int g = lane >> 3, r = lane & 7;

    for (int ch = 0; ch < nchunks; ch++) {
        if (ch + 1 < nchunks) CP_WAIT1(); else CP_WAIT0();
        __syncthreads();
        uint32_t base = sb + (ch & 1) * STG;

#pragma unroll
        for (int ks = 0; ks < 4; ks++) {
            uint32_t ah[2][4], al[2][4];
#pragma unroll
            for (int mt = 0; mt < 2; mt++) {
                int row = mw + (mt << 4) + ((g & 1) << 3) + r;
                int cb = (ks << 5) + ((g >> 1) << 4);
                uint32_t so = swz((uint32_t)(row * 128 + cb));
                ldmx4(ah[mt], base + P_AHI + so);
                ldmx4(al[mt], base + P_ALO + so);
            }
            uint32_t bh[8][2], bl[8][2];
#pragma unroll
            for (int p = 0; p < 4; p++) {
                int row = nw + (p << 4) + ((g >> 1) << 3) + r;
                int cb = (ks << 5) + ((g & 1) << 4);
                uint32_t so = swz((uint32_t)(row * 128 + cb));
                uint32_t t4[4];
                ldmx4(t4, base + P_BHI + so);      // non-trans: B is [N,K]
                bh[2 * p][0] = t4[0]; bh[2 * p][1] = t4[1];
                bh[2 * p + 1][0] = t4[2]; bh[2 * p + 1][1] = t4[3];
                ldmx4(t4, base + P_BLO + so);
                bl[2 * p][0] = t4[0]; bl[2 * p][1] = t4[1];
                bl[2 * p + 1][0] = t4[2]; bl[2 * p + 1][1] = t4[3];
            }
#pragma unroll
            for (int mt = 0; mt < 2; mt++)
#pragma unroll
                for (int nt = 0; nt < 8; nt++) {
                    hmma(acc[mt][nt], ah[mt], bh[nt]);
                    hmma(acc[mt][nt], ah[mt], bl[nt]);
                    hmma(acc[mt][nt], al[mt], bh[nt]);
                }
        }
        if (ch + 2 < nchunks) {
            __syncthreads();
            load_stage(ch + 2, (ch + 2) & 1);
        }
    }

    // epilogue
#pragma unroll
    for (int mt = 0; mt < 2; mt++) {
        int r0 = m0 + mw + (mt << 4) + (lane >> 2);
#pragma unroll
        for (int nt = 0; nt < 8; nt++) {
            int col = n0 + nw + (nt << 3) + ((lane & 3) << 1);
            float b0 = bias[col], b1 = bias[col + 1];
            float v0 = acc[mt][nt][0] + b0;
            float v1 = acc[mt][nt][1] + b1;
            float v2 = acc[mt][nt][2] + b0;
            float v3 = acc[mt][nt][3] + b1;
            if (ACT == 1) {
                v0 = 0.5f * v0 * (1.f + erff(v0 * 0.70710678118654752f));
                v1 = 0.5f * v1 * (1.f + erff(v1 * 0.70710678118654752f));
                v2 = 0.5f * v2 * (1.f + erff(v2 * 0.70710678118654752f));
                v3 = 0.5f * v3 * (1.f + erff(v3 * 0.70710678118654752f));
            }
            if (WF32) {
                float2 p0 = {v0, v1}, p1 = {v2, v3};
                *(float2*)&C[(long)r0 * ldC + col] = p0;
                *(float2*)&C[(long)(r0 + 8) * ldC + col] = p1;
            }
            if (WBF16) {
                __nv_bfloat16 h0, l0, h1, l1;
                split_bf16(v0, h0, l0); split_bf16(v1, h1, l1);
                __nv_bfloat162 hh = {h0, h1}, ll = {l0, l1};
                *(uint32_t*)&Chi[(long)r0 * ldC + col] = *(uint32_t*)&hh;
                *(uint32_t*)&Clo[(long)r0 * ldC + col] = *(uint32_t*)&ll;
                split_bf16(v2, h0, l0); split_bf16(v3, h1, l1);
                __nv_bfloat162 hh2 = {h0, h1}, ll2 = {l0, l1};
                *(uint32_t*)&Chi[(long)(r0 + 8) * ldC + col] = *(uint32_t*)&hh2;
                *(uint32_t*)&Clo[(long)(r0 + 8) * ldC + col] = *(uint32_t*)&ll2;
            }
        }
    }
}

// ---------------- banded attention (fp32 in from qkv buf, bf16 hi/lo out) ----------------
__global__ void __launch_bounds__(256)
attn_kernel(const float* __restrict__ qkv, const int* __restrict__ mask,
            __nv_bfloat16* __restrict__ aoh, __nv_bfloat16* __restrict__ aol) {
    __shared__ __align__(16) float qs[64][68];
    __shared__ __align__(16) float ks[32][68];
    __shared__ __align__(16) float vs[32][68];
    __shared__ __align__(16) float ss[64][36];

    int c = blockIdx.x, h = blockIdx.y, tid = threadIdx.x;
    int q0 = c * 64;
    int base = h * DH;

#pragma unroll
    for (int i = 0; i < 4; i++) {
        int idx = tid + i * 256;
        int r = idx >> 4, dq = (idx & 15) << 2;
        float4 qv = *(const float4*)&qkv[(q0 + r) * QKVD + base + dq];
        qv.x *= 0.125f; qv.y *= 0.125f; qv.z *= 0.125f; qv.w *= 0.125f;
        *(float4*)&qs[r][dq] = qv;
    }
    int ql = tid >> 2;
    int quad = tid & 3;
    int dg = quad << 4;
    float m = -1e30f, l = 0.f;
    float acc[16] = {};
    __syncthreads();

#pragma unroll 1
    for (int t = 0; t < (2 * WIN + 64) / 32; t++) {
        int j0 = q0 - WIN + t * 32;
        if (j0 + 32 <= 0 || j0 >= SEQ) continue;

#pragma unroll
        for (int i = 0; i < 2; i++) {
            int idx = tid + i * 256;
            int r = idx >> 4, dq = (idx & 15) << 2;
            int kj = j0 + r;
            if (kj >= 0 && kj < SEQ) {
                *(float4*)&ks[r][dq] = *(const float4*)&qkv[kj * QKVD + 768 + base + dq];
                *(float4*)&vs[r][dq] = *(const float4*)&qkv[kj * QKVD + 1536 + base + dq];
            } else {
                float4 z = {0.f, 0.f, 0.f, 0.f};
                *(float4*)&ks[r][dq] = z;
                *(float4*)&vs[r][dq] = z;
            }
        }
        __syncthreads();

        float sc[8];
#pragma unroll
        for (int j = 0; j < 8; j++) sc[j] = 0.f;
#pragma unroll
        for (int d = 0; d < DH; d += 4) {
            float4 qv = *(const float4*)&qs[ql][d];
#pragma unroll
            for (int j = 0; j < 8; j++) {
                float4 kv = *(const float4*)&ks[quad + (j << 2)][d];
                sc[j] += qv.x * kv.x + qv.y * kv.y + qv.z * kv.z + qv.w * kv.w;
            }
        }
        int qi = q0 + ql;
        float tm = -1e30f;
#pragma unroll
        for (int j = 0; j < 8; j++) {
            int kj = j0 + quad + (j << 2);
            bool valid = (kj >= 0) && (kj < SEQ) &&
                         (qi - kj <= WIN) && (kj - qi <= WIN) && (mask[kj] != 0);
            if (!valid) sc[j] = -1e9f;
            tm = fmaxf(tm, sc[j]);
        }
        tm = fmaxf(tm, __shfl_xor_sync(0xffffffffu, tm, 1));
        tm = fmaxf(tm, __shfl_xor_sync(0xffffffffu, tm, 2));
        float mn = fmaxf(m, tm);
        float scl = __expf(m - mn);
        float ps = 0.f;
#pragma unroll
        for (int j = 0; j < 8; j++) {
            float p = __expf(sc[j] - mn);
            ss[ql][quad + (j << 2)] = p;
            ps += p;
        }
        ps += __shfl_xor_sync(0xffffffffu, ps, 1);
        ps += __shfl_xor_sync(0xffffffffu, ps, 2);
        m = mn;
        l = l * scl + ps;
#pragma unroll
        for (int i = 0; i < 16; i++) acc[i] *= scl;
        __syncthreads();

#pragma unroll 4
        for (int kk = 0; kk < 32; kk++) {
            float p = ss[ql][kk];
#pragma unroll
            for (int i = 0; i < 16; i += 4) {
                float4 vv = *(const float4*)&vs[kk][dg + i];
                acc[i]     += p * vv.x;
                acc[i + 1] += p * vv.y;
                acc[i + 2] += p * vv.z;
                acc[i + 3] += p * vv.w;
            }
        }
        __syncthreads();
    }

    float inv = 1.f / l;
    uint32_t ph[8], pl[8];
#pragma unroll
    for (int i = 0; i < 8; i++) {
        __nv_bfloat16 h0, l0, h1, l1;
        split_bf16(acc[2 * i] * inv, h0, l0);
        split_bf16(acc[2 * i + 1] * inv, h1, l1);
        __nv_bfloat162 hh = {h0, h1}, ll = {l0, l1};
        ph[i] = *(uint32_t*)&hh;
        pl[i] = *(uint32_t*)&ll;
    }
    long o = (long)(q0 + ql) * DMODEL + base + dg;
#pragma unroll
    for (int j = 0; j < 2; j++) {
        *(uint4*)((char*)aoh + o * 2 + j * 16) = *(uint4*)&ph[j * 4];
        *(uint4*)((char*)aol + o * 2 + j * 16) = *(uint4*)&pl[j * 4];
    }
}

// ---------------- final extract ----------------
__global__ void out_kernel(float* __restrict__ out) {
    out[threadIdx.x] = g_h[threadIdx.x];
}

// ---------------- launcher ----------------
extern "C" void kernel_launch(void* const* d_in, const int* in_sizes, int n_in,
                              void* d_out, int out_size) {
    const int*   ids = (const int*)  d_in[0];
    const int*   am  = (const int*)  d_in[1];
    const float* we  = (const float*)d_in[2];
    const float* pe  = (const float*)d_in[3];
    const float* te  = (const float*)d_in[4];
    const float* eg  = (const float*)d_in[5];
    const float* eb  = (const float*)d_in[6];
    const float* Wq  = (const float*)d_in[7];
    const float* bq  = (const float*)d_in[8];
    const float* Wk  = (const float*)d_in[9];
    const float* bk  = (const float*)d_in[10];
    const float* Wv  = (const float*)d_in[11];
    const float* bv  = (const float*)d_in[12];
    const float* Wo  = (const float*)d_in[13];
    const float* bo  = (const float*)d_in[14];
    const float* g1  = (const float*)d_in[15];
    const float* b1  = (const float*)d_in[16];
    const float* W1  = (const float*)d_in[17];
    const float* c1  = (const float*)d_in[18];
    const float* W2  = (const float*)d_in[19];
    const float* c2  = (const float*)d_in[20];
    const float* g2  = (const float*)d_in[21];
    const float* b2  = (const float*)d_in[22];

    float *h, *qkv, *t2, *bqkv;
    __nv_bfloat16 *hhi, *hlo, *aohi, *aolo, *ffhi, *fflo;
    __nv_bfloat16 *wqkvh, *wqkvl, *woh, *wol, *w1h, *w1l, *w2h, *w2l;
    cudaGetSymbolAddress((void**)&h,    g_h);
    cudaGetSymbolAddress((void**)&qkv,  g_qkv);
    cudaGetSymbolAddress((void**)&t2,   g_t2);
    cudaGetSymbolAddress((void**)&bqkv, g_bqkv);
    cudaGetSymbolAddress((void**)&hhi,  g_h_hi);
    cudaGetSymbolAddress((void**)&hlo,  g_h_lo);
    cudaGetSymbolAddress((void**)&aohi, g_ao_hi);
    cudaGetSymbolAddress((void**)&aolo, g_ao_lo);
    cudaGetSymbolAddress((void**)&ffhi, g_ff_hi);
    cudaGetSymbolAddress((void**)&fflo, g_ff_lo);
    cudaGetSymbolAddress((void**)&wqkvh, g_wqkv_hi);
    cudaGetSymbolAddress((void**)&wqkvl, g_wqkv_lo);
    cudaGetSymbolAddress((void**)&woh,  g_wo_hi);
    cudaGetSymbolAddress((void**)&wol,  g_wo_lo);
    cudaGetSymbolAddress((void**)&w1h,  g_w1_hi);
    cudaGetSymbolAddress((void**)&w1l,  g_w1_lo);
    cudaGetSymbolAddress((void**)&w2h,  g_w2_hi);
    cudaGetSymbolAddress((void**)&w2l,  g_w2_lo);

    cudaFuncSetAttribute(mgemm<0, 1, 0>, cudaFuncAttributeMaxDynamicSharedMemorySize, 2 * STG);
    cudaFuncSetAttribute(mgemm<1, 0, 1>, cudaFuncAttributeMaxDynamicSharedMemorySize, 2 * STG);

    // one-time per replay: weight transpose + split
    dim3 gp(DMODEL / 32, DMODEL / 32, NLAYER);
    wconv_kernel<<<gp, 256>>>(Wq, wqkvh, wqkvl, DMODEL, DMODEL,
                              (long)DMODEL * DMODEL, (long)QKVD * DMODEL, 0);
    wconv_kernel<<<gp, 256>>>(Wk, wqkvh, wqkvl, DMODEL, DMODEL,
                              (long)DMODEL * DMODEL, (long)QKVD * DMODEL, 768);
    wconv_kernel<<<gp, 256>>>(Wv, wqkvh, wqkvl, DMODEL, DMODEL,
                              (long)DMODEL * DMODEL, (long)QKVD * DMODEL, 1536);
    wconv_kernel<<<gp, 256>>>(Wo, woh, wol, DMODEL, DMODEL,
                              (long)DMODEL * DMODEL, (long)DMODEL * DMODEL, 0);
    dim3 g1d(FFDIM / 32, DMODEL / 32, NLAYER);
    wconv_kernel<<<g1d, 256>>>(W1, w1h, w1l, DMODEL, FFDIM,
                               (long)DMODEL * FFDIM, (long)FFDIM * DMODEL, 0);
    dim3 g2d(DMODEL / 32, FFDIM / 32, NLAYER);
    wconv_kernel<<<g2d, 256>>>(W2, w2h, w2l, FFDIM, DMODEL,
                               (long)FFDIM * DMODEL, (long)DMODEL * FFDIM, 0);
    bmerge_kernel<<<NLAYER, 768>>>(bq, bk, bv);

    pos_ids_kernel<<<1, 256>>>(am);
    embed_kernel<<<SEQ, 192>>>(ids, we, pe, te, t2);
    ln_kernel<<<SEQ, 192>>>(t2, nullptr, eg, eb, h, hhi, hlo);

    dim3 gQKV(QKVD / 128, SEQ / 128);    // 18 x 16
    dim3 gD  (DMODEL / 128, SEQ / 128);  // 6  x 16
    dim3 gFF (FFDIM / 128, SEQ / 128);   // 24 x 16
    dim3 gAttn(SEQ / 64, NHEAD);

    for (int l = 0; l < NLAYER; l++) {
        mgemm<0, 1, 0><<<gQKV, 256, 2 * STG>>>(
            hhi, hlo, wqkvh + (long)l * QKVD * DMODEL, wqkvl + (long)l * QKVD * DMODEL,
            bqkv + l * QKVD, qkv, nullptr, nullptr, DMODEL, QKVD);

        attn_kernel<<<gAttn, 256>>>(qkv, am, aohi, aolo);

        mgemm<0, 1, 0><<<gD, 256, 2 * STG>>>(
            aohi, aolo, woh + (long)l * DMODEL * DMODEL, wol + (long)l * DMODEL * DMODEL,
            bo + l * DMODEL, t2, nullptr, nullptr, DMODEL, DMODEL);

        ln_kernel<<<SEQ, 192>>>(t2, h, g1 + l * DMODEL, b1 + l * DMODEL, h, hhi, hlo);

        mgemm<1, 0, 1><<<gFF, 256, 2 * STG>>>(
            hhi, hlo, w1h + (long)l * FFDIM * DMODEL, w1l + (long)l * FFDIM * DMODEL,
            c1 + l * FFDIM, nullptr, ffhi, fflo, DMODEL, FFDIM);

        mgemm<0, 1, 0><<<gD, 256, 2 * STG>>>(
            ffhi, fflo, w2h + (long)l * DMODEL * FFDIM, w2l + (long)l * DMODEL * FFDIM,
            c2 + l * DMODEL, t2, nullptr, nullptr, FFDIM, DMODEL);

        ln_kernel<<<SEQ, 192>>>(t2, h, g2 + l * DMODEL, b2 + l * DMODEL, h, hhi, hlo);
    }

    out_kernel<<<1, DMODEL>>>((float*)d_out);
}